// round 2
// baseline (speedup 1.0000x reference)
#include <cuda_runtime.h>
#include <math_constants.h>

#define B_   4
#define C2_  64
#define C_   128
#define N_   4096

// Scratch (allocation-free rule: __device__ globals)
__device__ float g_K[B_*C2_*N_];  // theta(concat(H,L))  -> keys   [b][c][n]
__device__ float g_Q[B_*C2_*N_];  // phi(concat(H,L))    -> queries[b][c][m]
__device__ float g_V[B_*C2_*N_];  // g(L)                -> values [b][c][n]
__device__ float g_E[B_*C2_*N_];  // attention output    [b][c][n]

// ---- packed f32x2 helpers (Blackwell FFMA2 path) ----
__device__ __forceinline__ unsigned long long pk2(float x, float y) {
    unsigned long long r;
    asm("mov.b64 %0, {%1,%2};" : "=l"(r) : "f"(x), "f"(y));
    return r;
}
__device__ __forceinline__ float2 upk2(unsigned long long v) {
    float2 f;
    asm("mov.b64 {%0,%1}, %2;" : "=f"(f.x), "=f"(f.y) : "l"(v));
    return f;
}
__device__ __forceinline__ void fma2(unsigned long long &d, unsigned long long a, unsigned long long b) {
    asm("fma.rn.f32x2 %0, %1, %2, %0;" : "+l"(d) : "l"(a), "l"(b));
}

// ============================================================
// Kernel 1: 1x1 conv projections as GEMMs.
//   proj 0: g_K = theta_w[64,128] @ concat(H,L) + theta_b
//   proj 1: g_Q = phi_w  [64,128] @ concat(H,L) + phi_b
//   proj 2: g_V = g_w    [64, 64] @ L           + g_b
// grid (32 pixel-tiles, 3 projs, 4 batch), 256 threads.
// ============================================================
__global__ void __launch_bounds__(256) proj_kernel(
    const float* __restrict__ Hp, const float* __restrict__ Lp,
    const float* __restrict__ tw, const float* __restrict__ tb,
    const float* __restrict__ pw, const float* __restrict__ pb,
    const float* __restrict__ gw, const float* __restrict__ gb)
{
    extern __shared__ float sm[];
    float* sX = sm;              // [IC][128]
    float* sW = sm + 128 * 128;  // [64][IC]

    const int proj = blockIdx.y;
    const int b    = blockIdx.z;
    const int p0   = blockIdx.x << 7;
    const int tid  = threadIdx.x;

    const float* W; const float* bias; float* dst; int IC;
    if (proj == 0)      { W = tw; bias = tb; dst = g_K; IC = C_;  }
    else if (proj == 1) { W = pw; bias = pb; dst = g_Q; IC = C_;  }
    else                { W = gw; bias = gb; dst = g_V; IC = C2_; }

    for (int i = tid; i < IC * 128; i += 256) {
        int c = i >> 7, p = i & 127;
        const float* src = (proj == 2) ? Lp : ((c < 64) ? Hp : Lp);
        sX[i] = src[(((b << 6) + (c & 63)) << 12) + p0 + p];
    }
    for (int i = tid; i < 64 * IC; i += 256) sW[i] = W[i];
    __syncthreads();

    const int to = tid >> 4;   // output-channel group (4 ch)
    const int tp = tid & 15;   // pixel-pair group

    unsigned long long acc[4][4];
    #pragma unroll
    for (int i = 0; i < 4; i++)
        #pragma unroll
        for (int j = 0; j < 4; j++) acc[i][j] = 0ULL;

    for (int c = 0; c < IC; c++) {
        unsigned long long wv[4], x2[4];
        #pragma unroll
        for (int i = 0; i < 4; i++) {
            float w = sW[(4 * to + i) * IC + c];
            wv[i] = pk2(w, w);
        }
        #pragma unroll
        for (int j = 0; j < 4; j++)
            x2[j] = *(const unsigned long long*)&sX[(c << 7) + 2 * tp + (j << 5)];
        #pragma unroll
        for (int i = 0; i < 4; i++)
            #pragma unroll
            for (int j = 0; j < 4; j++) fma2(acc[i][j], wv[i], x2[j]);
    }

    #pragma unroll
    for (int i = 0; i < 4; i++) {
        int o = 4 * to + i;
        float bo = bias[o];
        #pragma unroll
        for (int j = 0; j < 4; j++) {
            float2 r = upk2(acc[i][j]);
            r.x += bo; r.y += bo;
            *(float2*)&dst[(((b << 6) + o) << 12) + p0 + 2 * tp + (j << 5)] = r;
        }
    }
}

// ============================================================
// Kernel 2: fused attention (flash-style, softmax over keys n).
//   S[n,m] = sum_c K[c,n]*Q[c,m]   (unscaled)
//   P      = softmax_n(S)          (online)
//   E[c,m] = sum_n V[c,n]*P[n,m], finally / rowsum
// grid (32 query-tiles, 4 batch), 256 threads, one block per SM.
// ============================================================
__global__ void __launch_bounds__(256, 1) attn_kernel()
{
    extern __shared__ float sm[];
    float* sQ = sm;                 // [64][128]
    float* sK = sm + 8192;          // [64][128]
    float* sV = sm + 16384;         // [64][128]
    float* sP = sm + 24576;         // [128][130] (pad kills bank conflicts)
    float* sAlpha = sm + 24576 + 128 * 130;  // [128]
    float* sSum   = sAlpha + 128;            // [128]

    const int tid = threadIdx.x;
    const int b   = blockIdx.y;
    const int m0  = blockIdx.x << 7;

    // Load Q tile once
    for (int i = tid; i < 8192; i += 256) {
        int c = i >> 7, m = i & 127;
        sQ[i] = g_Q[(((b << 6) + c) << 12) + m0 + m];
    }

    // S-phase mapping: n = tn + 16*ii (ii 0..7), m pairs = 2*tm + 32*jj (jj 0..3)
    const int tn = tid & 15, tm = tid >> 4;
    // E-phase mapping: c = 4*cg + i, m pairs = 2*mg + 32*jj
    const int cg = tid >> 4, mg = tid & 15;

    float2 mr[4], lr[4];
    #pragma unroll
    for (int j = 0; j < 4; j++) {
        mr[j] = make_float2(-CUDART_INF_F, -CUDART_INF_F);
        lr[j] = make_float2(0.f, 0.f);
    }
    unsigned long long e2[4][4];
    #pragma unroll
    for (int i = 0; i < 4; i++)
        #pragma unroll
        for (int j = 0; j < 4; j++) e2[i][j] = 0ULL;

    for (int kt = 0; kt < 32; kt++) {
        const int n0 = kt << 7;
        __syncthreads();  // previous E-phase finished with sK/sV/sP
        for (int i = tid; i < 8192; i += 256) {
            int c = i >> 7, n = i & 127;
            int gi = (((b << 6) + c) << 12) + n0 + n;
            sK[i] = g_K[gi];
            sV[i] = g_V[gi];
        }
        __syncthreads();

        // ---- S = K^T Q over this tile ----
        unsigned long long s2[8][4];
        #pragma unroll
        for (int ii = 0; ii < 8; ii++)
            #pragma unroll
            for (int jj = 0; jj < 4; jj++) s2[ii][jj] = 0ULL;

        for (int c = 0; c < 64; c++) {
            unsigned long long kk[8], q2[4];
            #pragma unroll
            for (int ii = 0; ii < 8; ii++) {
                float k = sK[(c << 7) + tn + (ii << 4)];
                kk[ii] = pk2(k, k);
            }
            #pragma unroll
            for (int jj = 0; jj < 4; jj++)
                q2[jj] = *(const unsigned long long*)&sQ[(c << 7) + 2 * tm + (jj << 5)];
            #pragma unroll
            for (int ii = 0; ii < 8; ii++)
                #pragma unroll
                for (int jj = 0; jj < 4; jj++) fma2(s2[ii][jj], kk[ii], q2[jj]);
        }

        // ---- online softmax over n (column reduce across tn lanes) ----
        #pragma unroll
        for (int jj = 0; jj < 4; jj++) {
            float2 cm = upk2(s2[0][jj]);
            #pragma unroll
            for (int ii = 1; ii < 8; ii++) {
                float2 f = upk2(s2[ii][jj]);
                cm.x = fmaxf(cm.x, f.x); cm.y = fmaxf(cm.y, f.y);
            }
            #pragma unroll
            for (int off = 1; off < 16; off <<= 1) {
                cm.x = fmaxf(cm.x, __shfl_xor_sync(0xffffffffu, cm.x, off));
                cm.y = fmaxf(cm.y, __shfl_xor_sync(0xffffffffu, cm.y, off));
            }
            float2 mo = mr[jj];
            float2 mn = make_float2(fmaxf(mo.x, cm.x), fmaxf(mo.y, cm.y));
            float2 al = make_float2(__expf(mo.x - mn.x), __expf(mo.y - mn.y));
            float2 cs = make_float2(0.f, 0.f);
            #pragma unroll
            for (int ii = 0; ii < 8; ii++) {
                float2 f = upk2(s2[ii][jj]);
                float2 p = make_float2(__expf(f.x - mn.x), __expf(f.y - mn.y));
                cs.x += p.x; cs.y += p.y;
                *(float2*)&sP[(tn + (ii << 4)) * 130 + 2 * tm + (jj << 5)] = p;
            }
            #pragma unroll
            for (int off = 1; off < 16; off <<= 1) {
                cs.x += __shfl_xor_sync(0xffffffffu, cs.x, off);
                cs.y += __shfl_xor_sync(0xffffffffu, cs.y, off);
            }
            lr[jj].x = lr[jj].x * al.x + cs.x;
            lr[jj].y = lr[jj].y * al.y + cs.y;
            mr[jj] = mn;
            if (tn == 0) *(float2*)&sAlpha[2 * tm + (jj << 5)] = al;
        }
        __syncthreads();

        // ---- E = E*alpha + V @ P ----
        #pragma unroll
        for (int jj = 0; jj < 4; jj++) {
            float2 al = *(const float2*)&sAlpha[2 * mg + (jj << 5)];
            #pragma unroll
            for (int i = 0; i < 4; i++) {
                float2 f = upk2(e2[i][jj]);
                f.x *= al.x; f.y *= al.y;
                e2[i][jj] = pk2(f.x, f.y);
            }
        }
        for (int n = 0; n < 128; n++) {
            unsigned long long vv[4], p2[4];
            #pragma unroll
            for (int i = 0; i < 4; i++) {
                float v = sV[((4 * cg + i) << 7) + n];
                vv[i] = pk2(v, v);
            }
            #pragma unroll
            for (int jj = 0; jj < 4; jj++)
                p2[jj] = *(const unsigned long long*)&sP[n * 130 + 2 * mg + (jj << 5)];
            #pragma unroll
            for (int i = 0; i < 4; i++)
                #pragma unroll
                for (int jj = 0; jj < 4; jj++) fma2(e2[i][jj], vv[i], p2[jj]);
        }
    }

    // finalize: divide by row sums, write E
    if (tn == 0) {
        #pragma unroll
        for (int jj = 0; jj < 4; jj++)
            *(float2*)&sSum[2 * tm + (jj << 5)] = lr[jj];
    }
    __syncthreads();
    #pragma unroll
    for (int jj = 0; jj < 4; jj++) {
        float2 s = *(const float2*)&sSum[2 * mg + (jj << 5)];
        float2 inv = make_float2(1.f / s.x, 1.f / s.y);
        #pragma unroll
        for (int i = 0; i < 4; i++) {
            float2 f = upk2(e2[i][jj]);
            f.x *= inv.x; f.y *= inv.y;
            *(float2*)&g_E[(((b << 6) + 4 * cg + i) << 12) + m0 + 2 * mg + (jj << 5)] = f;
        }
    }
}

// ============================================================
// Kernel 3: 3x3 conv (SAME) + BN(inference) + ReLU + residual.
// All weights staged in smem as [ic*9+kk][oc] (oc contiguous for f32x2).
// grid (32 row-strips, 4 batch), 128 threads = 2 rows x 64 cols, 1 px/thread.
// ============================================================
__global__ void __launch_bounds__(128, 1) conv_kernel(
    const float* __restrict__ Hp,
    const float* __restrict__ cw, const float* __restrict__ cb,
    const float* __restrict__ gamma, const float* __restrict__ beta,
    const float* __restrict__ mean,  const float* __restrict__ var,
    float* __restrict__ out)
{
    extern __shared__ float sW[];  // [64*9][64] = 147456 B
    const int tid = threadIdx.x;
    const int b   = blockIdx.y;
    const int y0  = blockIdx.x << 1;

    for (int i = tid; i < 64 * 64 * 9; i += 128) {
        int oc = i / 576;
        int rem = i - oc * 576;
        int ic = rem / 9;
        int kk = rem - ic * 9;
        sW[(ic * 9 + kk) * 64 + oc] = cw[i];
    }
    __syncthreads();

    const int y = y0 + (tid >> 6);
    const int x = tid & 63;

    unsigned long long acc2[32];
    #pragma unroll
    for (int i = 0; i < 32; i++) acc2[i] = 0ULL;

    for (int ic = 0; ic < 64; ic++) {
        const float* src = &g_E[(((b << 6) + ic) << 12)];
        float in9[9];
        #pragma unroll
        for (int dy = 0; dy < 3; dy++) {
            int yy = y + dy - 1;
            bool yok = (yy >= 0) && (yy < 64);
            #pragma unroll
            for (int dx = 0; dx < 3; dx++) {
                int xx = x + dx - 1;
                bool ok = yok && (xx >= 0) && (xx < 64);
                in9[dy * 3 + dx] = ok ? src[(yy << 6) + xx] : 0.f;
            }
        }
        #pragma unroll
        for (int kk = 0; kk < 9; kk++) {
            unsigned long long iv = pk2(in9[kk], in9[kk]);
            const float* wrow = &sW[(ic * 9 + kk) << 6];
            #pragma unroll
            for (int q = 0; q < 16; q++) {
                ulonglong2 w = *(const ulonglong2*)&wrow[q << 2];
                fma2(acc2[2 * q],     iv, w.x);
                fma2(acc2[2 * q + 1], iv, w.y);
            }
        }
    }

    const int pix = (y << 6) + x;
    #pragma unroll
    for (int q = 0; q < 32; q++) {
        float2 f = upk2(acc2[q]);
        #pragma unroll
        for (int h = 0; h < 2; h++) {
            int oc = 2 * q + h;
            float v = (h ? f.y : f.x) + cb[oc];
            float scale = gamma[oc] * rsqrtf(var[oc] + 1e-5f);
            v = (v - mean[oc]) * scale + beta[oc];
            v = fmaxf(v, 0.f);
            int idx = (((b << 6) + oc) << 12) + pix;
            out[idx] = Hp[idx] + v;
        }
    }
}

// ============================================================
extern "C" void kernel_launch(void* const* d_in, const int* in_sizes, int n_in,
                              void* d_out, int out_size)
{
    const float* Hp    = (const float*)d_in[0];
    const float* Lp    = (const float*)d_in[1];
    const float* tw    = (const float*)d_in[2];
    const float* tb    = (const float*)d_in[3];
    const float* pw    = (const float*)d_in[4];
    const float* pb    = (const float*)d_in[5];
    const float* gw    = (const float*)d_in[6];
    const float* gb    = (const float*)d_in[7];
    const float* cw    = (const float*)d_in[8];
    const float* cb    = (const float*)d_in[9];
    const float* gamma = (const float*)d_in[10];
    const float* beta  = (const float*)d_in[11];
    const float* mean  = (const float*)d_in[12];
    const float* var   = (const float*)d_in[13];
    float* out = (float*)d_out;

    const int smem_proj = (128 * 128 + 64 * 128) * 4;            // 98304
    const int smem_attn = (24576 + 128 * 130 + 256) * 4;         // 165888
    const int smem_conv = 64 * 64 * 9 * 4;                       // 147456

    cudaFuncSetAttribute(proj_kernel, cudaFuncAttributeMaxDynamicSharedMemorySize, smem_proj);
    cudaFuncSetAttribute(attn_kernel, cudaFuncAttributeMaxDynamicSharedMemorySize, smem_attn);
    cudaFuncSetAttribute(conv_kernel, cudaFuncAttributeMaxDynamicSharedMemorySize, smem_conv);

    proj_kernel<<<dim3(32, 3, 4), 256, smem_proj>>>(Hp, Lp, tw, tb, pw, pb, gw, gb);
    attn_kernel<<<dim3(32, 4), 256, smem_attn>>>();
    conv_kernel<<<dim3(32, 4), 128, smem_conv>>>(Hp, cw, cb, gamma, beta, mean, var, out);
}

// round 4
// speedup vs baseline: 2.5282x; 2.5282x over previous
#include <cuda_runtime.h>
#include <cuda_bf16.h>
typedef unsigned int u32; typedef unsigned long long u64;

#define NELEM (4*4096*64)
__device__ __nv_bfloat16 g_Khi[NELEM], g_Klo[NELEM];   // [b][n][c]
__device__ __nv_bfloat16 g_Qhi[NELEM], g_Qlo[NELEM];   // [b][m][c]
__device__ __nv_bfloat16 g_Vhi[NELEM], g_Vlo[NELEM];   // [b][n][c]
__device__ float g_E[NELEM];                            // [b][c][n]

// swizzled byte offset inside a [128 rows][64 bf16] tile (rows of 128B, 8 chunks of 16B)
#define SWZ(row, chunk) (((u32)(row) << 7) + ((u32)(((chunk) ^ ((row) & 7))) << 4))

__device__ __forceinline__ u32 smem_u32(const void* p) {
    u32 a; asm("{ .reg .u64 t; cvta.to.shared.u64 t, %1; cvt.u32.u64 %0, t; }" : "=r"(a) : "l"(p)); return a;
}
__device__ __forceinline__ void cpa16(u32 dst, const void* src) {
    asm volatile("cp.async.cg.shared.global [%0], [%1], 16;" :: "r"(dst), "l"(src));
}
__device__ __forceinline__ void cpa_commit() { asm volatile("cp.async.commit_group;"); }
__device__ __forceinline__ void cpa_wait0()  { asm volatile("cp.async.wait_group 0;"); }

__device__ __forceinline__ void ldsm4(u32* r, u32 a) {
    asm volatile("ldmatrix.sync.aligned.m8n8.x4.shared.b16 {%0,%1,%2,%3},[%4];"
        : "=r"(r[0]), "=r"(r[1]), "=r"(r[2]), "=r"(r[3]) : "r"(a));
}
__device__ __forceinline__ void ldsm4t(u32* r, u32 a) {
    asm volatile("ldmatrix.sync.aligned.m8n8.x4.trans.shared.b16 {%0,%1,%2,%3},[%4];"
        : "=r"(r[0]), "=r"(r[1]), "=r"(r[2]), "=r"(r[3]) : "r"(a));
}
__device__ __forceinline__ void mma_bf16(float* d, const u32* a, u32 b0, u32 b1) {
    asm volatile("mma.sync.aligned.m16n8k16.row.col.f32.bf16.bf16.f32 "
        "{%0,%1,%2,%3},{%4,%5,%6,%7},{%8,%9},{%0,%1,%2,%3};"
        : "+f"(d[0]), "+f"(d[1]), "+f"(d[2]), "+f"(d[3])
        : "r"(a[0]), "r"(a[1]), "r"(a[2]), "r"(a[3]), "r"(b0), "r"(b1));
}
__device__ __forceinline__ u32 pack_bf16(float lo, float hi) {
    u32 r; asm("cvt.rn.bf16x2.f32 %0, %1, %2;" : "=r"(r) : "f"(hi), "f"(lo)); return r;
}

// ================= Kernel 1: projections -> split bf16 (all [b][row][c]) ==========
__global__ void __launch_bounds__(256) proj_kernel(
    const float* __restrict__ Hp, const float* __restrict__ Lp,
    const float* __restrict__ tw, const float* __restrict__ tb,
    const float* __restrict__ pw, const float* __restrict__ pb,
    const float* __restrict__ gw, const float* __restrict__ gb)
{
    extern __shared__ float sm[];
    float* sX = sm;              // [IC][128]
    float* sW = sm + 128 * 128;  // [64][IC]
    const int proj = blockIdx.y, b = blockIdx.z, p0 = blockIdx.x << 7, tid = threadIdx.x;
    const float* W; const float* bias; int IC;
    if (proj == 0)      { W = tw; bias = tb; IC = 128; }
    else if (proj == 1) { W = pw; bias = pb; IC = 128; }
    else                { W = gw; bias = gb; IC = 64;  }

    for (int i = tid; i < IC * 128; i += 256) {
        int c = i >> 7, p = i & 127;
        const float* src = (proj == 2) ? Lp : ((c < 64) ? Hp : Lp);
        sX[i] = src[(((b << 6) + (c & 63)) << 12) + p0 + p];
    }
    for (int i = tid; i < 64 * IC; i += 256) sW[i] = W[i];
    __syncthreads();

    const int to = tid >> 4, tp = tid & 15;
    float2 acc[4][4];
    #pragma unroll
    for (int i = 0; i < 4; i++)
        #pragma unroll
        for (int j = 0; j < 4; j++) acc[i][j] = make_float2(0.f, 0.f);
    for (int c = 0; c < IC; c++) {
        float wv[4]; float2 x2[4];
        #pragma unroll
        for (int i = 0; i < 4; i++) wv[i] = sW[(4 * to + i) * IC + c];
        #pragma unroll
        for (int j = 0; j < 4; j++) x2[j] = *(const float2*)&sX[(c << 7) + 2 * tp + (j << 5)];
        #pragma unroll
        for (int i = 0; i < 4; i++)
            #pragma unroll
            for (int j = 0; j < 4; j++) {
                acc[i][j].x = fmaf(wv[i], x2[j].x, acc[i][j].x);
                acc[i][j].y = fmaf(wv[i], x2[j].y, acc[i][j].y);
            }
    }
    __syncthreads();
    __nv_bfloat16* tHi = (__nv_bfloat16*)sm;
    __nv_bfloat16* tLo = (__nv_bfloat16*)((char*)sm + 16384);
    #pragma unroll
    for (int i = 0; i < 4; i++) {
        int o = 4 * to + i; float bo = bias[o];
        #pragma unroll
        for (int j = 0; j < 4; j++) {
            int px = 2 * tp + (j << 5);
            float vx = acc[i][j].x + bo, vy = acc[i][j].y + bo;
            __nv_bfloat16 hx = __float2bfloat16_rn(vx), hy = __float2bfloat16_rn(vy);
            tHi[px * 64 + o] = hx;           tHi[(px + 1) * 64 + o] = hy;
            tLo[px * 64 + o] = __float2bfloat16_rn(vx - __bfloat162float(hx));
            tLo[(px + 1) * 64 + o] = __float2bfloat16_rn(vy - __bfloat162float(hy));
        }
    }
    __syncthreads();
    __nv_bfloat16* dHi = (proj == 0) ? g_Khi : (proj == 1) ? g_Qhi : g_Vhi;
    __nv_bfloat16* dLo = (proj == 0) ? g_Klo : (proj == 1) ? g_Qlo : g_Vlo;
    uint4* dh = (uint4*)(dHi + ((size_t)b * 4096 + p0) * 64);
    uint4* dl = (uint4*)(dLo + ((size_t)b * 4096 + p0) * 64);
    const uint4* shh = (const uint4*)tHi; const uint4* sll = (const uint4*)tLo;
    for (int u = tid; u < 1024; u += 256) { dh[u] = shh[u]; dl[u] = sll[u]; }
}

// ================= Kernel 2: HMMA flash attention (no-max single pass) =============
// smem: Qh 16K | Ql 16K | Kbuf0 (Kh+Kl 32K) | Kbuf1 32K | Vbuf0 32K | Vbuf1 32K = 160K
#define ATTN_SMEM 163840

__global__ void __launch_bounds__(256, 1) attn_kernel()
{
    extern __shared__ char smem[];
    const int tid = threadIdx.x, w = tid >> 5, l = tid & 31;
    const int b = blockIdx.y, m0 = blockIdx.x << 7;
    const u32 sb  = smem_u32(smem);
    const u32 sQh = sb, sQl = sb + 16384;
    const u32 sK0 = sb + 32768;   // + buf*32768 ; lo at +16384
    const u32 sV0 = sb + 98304;

    // prologue: Q + first K/V tile
    for (int u = tid; u < 1024; u += 256) {
        int row = u >> 3, ch = u & 7;
        size_t gq = ((size_t)(b * 4096 + m0 + row)) * 64 + ch * 8;
        size_t gk = ((size_t)(b * 4096 + row)) * 64 + ch * 8;
        u32 d = SWZ(row, ch);
        cpa16(sQh + d, g_Qhi + gq);
        cpa16(sQl + d, g_Qlo + gq);
        cpa16(sK0 + d, g_Khi + gk);
        cpa16(sK0 + 16384 + d, g_Klo + gk);
        cpa16(sV0 + d, g_Vhi + gk);
        cpa16(sV0 + 16384 + d, g_Vlo + gk);
    }
    cpa_commit(); cpa_wait0(); __syncthreads();

    // persistent Q fragments (A of GEMM1): rows R..R+15
    const int R = w << 4;
    u32 qh[4][4], ql[4][4];
    {
        int arow = R + (l & 15);
        #pragma unroll
        for (int kk = 0; kk < 4; kk++) {
            int chunk = kk * 2 + (l >> 4);
            ldsm4(qh[kk], sQh + SWZ(arow, chunk));
            ldsm4(ql[kk], sQl + SWZ(arow, chunk));
        }
    }

    float esum0 = 0.f, esum1 = 0.f;
    float eacc[8][4];
    #pragma unroll
    for (int j = 0; j < 8; j++)
        #pragma unroll
        for (int q = 0; q < 4; q++) eacc[j][q] = 0.f;

    const int krow  = (l & 7) + ((l & 16) ? 8 : 0);   // GEMM1 B lane row
    const int kcsel = (l >> 3) & 1;
    const int vrow  = (l & 7) + ((l & 8) ? 8 : 0);    // GEMM2 B lane row
    const int vcsel = (l >> 4) & 1;

    for (int kt = 0; kt < 32; kt++) {
        const u32 kb = sK0 + (u32)(kt & 1) * 32768;
        const u32 vb = sV0 + (u32)(kt & 1) * 32768;

        if (kt + 1 < 32) {   // prefetch next tile
            int n1 = (kt + 1) << 7;
            u32 kd = sK0 + (u32)((kt + 1) & 1) * 32768;
            u32 vd = sV0 + (u32)((kt + 1) & 1) * 32768;
            for (int u = tid; u < 1024; u += 256) {
                int row = u >> 3, ch = u & 7;
                size_t g = ((size_t)(b * 4096 + n1 + row)) * 64 + ch * 8;
                u32 d = SWZ(row, ch);
                cpa16(kd + d, g_Khi + g);
                cpa16(kd + 16384 + d, g_Klo + g);
                cpa16(vd + d, g_Vhi + g);
                cpa16(vd + 16384 + d, g_Vlo + g);
            }
            cpa_commit();
        }

        // ---- GEMM1: S[16 x 128] ----
        float s[16][4];
        #pragma unroll
        for (int nt = 0; nt < 16; nt++)
            #pragma unroll
            for (int q = 0; q < 4; q++) s[nt][q] = 0.f;

        #pragma unroll
        for (int nt2 = 0; nt2 < 8; nt2++) {
            #pragma unroll
            for (int kk = 0; kk < 4; kk++) {
                u32 kh[4], klo[4];
                int rr = nt2 * 16 + krow;
                int ch = kk * 2 + kcsel;
                ldsm4(kh,  kb + SWZ(rr, ch));
                ldsm4(klo, kb + 16384 + SWZ(rr, ch));
                mma_bf16(s[nt2 * 2 + 0], qh[kk], kh[0], kh[1]);
                mma_bf16(s[nt2 * 2 + 0], qh[kk], klo[0], klo[1]);
                mma_bf16(s[nt2 * 2 + 0], ql[kk], kh[0], kh[1]);
                mma_bf16(s[nt2 * 2 + 1], qh[kk], kh[2], kh[3]);
                mma_bf16(s[nt2 * 2 + 1], qh[kk], klo[2], klo[3]);
                mma_bf16(s[nt2 * 2 + 1], ql[kk], kh[2], kh[3]);
            }
        }

        // ---- softmax (no max-shift) + pack P into GEMM2 A-fragments ----
        u32 ph[8][4], pl[8][4];
        #pragma unroll
        for (int nt = 0; nt < 16; nt++) {
            float e0 = __expf(fminf(s[nt][0], 80.f));
            float e1 = __expf(fminf(s[nt][1], 80.f));
            float e2 = __expf(fminf(s[nt][2], 80.f));
            float e3 = __expf(fminf(s[nt][3], 80.f));
            esum0 += e0 + e1; esum1 += e2 + e3;
            u32 h01 = pack_bf16(e0, e1), h23 = pack_bf16(e2, e3);
            float r0 = e0 - __uint_as_float(h01 << 16);
            float r1 = e1 - __uint_as_float(h01 & 0xffff0000u);
            float r2 = e2 - __uint_as_float(h23 << 16);
            float r3 = e3 - __uint_as_float(h23 & 0xffff0000u);
            int t = nt >> 1, hf = (nt & 1) << 1;
            ph[t][hf + 0] = h01;  ph[t][hf + 1] = h23;
            pl[t][hf + 0] = pack_bf16(r0, r1);
            pl[t][hf + 1] = pack_bf16(r2, r3);
        }

        // ---- GEMM2: E[16 x 64] += P * V ----
        #pragma unroll
        for (int t = 0; t < 8; t++) {
            #pragma unroll
            for (int cb = 0; cb < 4; cb++) {
                u32 vh[4], vl[4];
                int rr = t * 16 + vrow;
                int ch = cb * 2 + vcsel;
                ldsm4t(vh, vb + SWZ(rr, ch));
                ldsm4t(vl, vb + 16384 + SWZ(rr, ch));
                mma_bf16(eacc[cb * 2 + 0], ph[t], vh[0], vh[1]);
                mma_bf16(eacc[cb * 2 + 0], ph[t], vl[0], vl[1]);
                mma_bf16(eacc[cb * 2 + 0], pl[t], vh[0], vh[1]);
                mma_bf16(eacc[cb * 2 + 1], ph[t], vh[2], vh[3]);
                mma_bf16(eacc[cb * 2 + 1], ph[t], vl[2], vl[3]);
                mma_bf16(eacc[cb * 2 + 1], pl[t], vh[2], vh[3]);
            }
        }

        cpa_wait0();
        __syncthreads();
    }

    // rowsum reduce across the 4 lanes sharing each row
    #pragma unroll
    for (int off = 1; off < 4; off <<= 1) {
        esum0 += __shfl_xor_sync(0xffffffffu, esum0, off);
        esum1 += __shfl_xor_sync(0xffffffffu, esum1, off);
    }
    float inv0 = 1.f / esum0, inv1 = 1.f / esum1;

    // transpose E via smem (reuse K buffers), write g_E[b][c][m]
    float* sE = (float*)(smem + 32768);   // [64][132]
    const int mloc = R + (l >> 2);
    const int c0 = 2 * (l & 3);
    #pragma unroll
    for (int j = 0; j < 8; j++) {
        int c = 8 * j + c0;
        sE[c * 132 + mloc]           = eacc[j][0] * inv0;
        sE[(c + 1) * 132 + mloc]     = eacc[j][1] * inv0;
        sE[c * 132 + mloc + 8]       = eacc[j][2] * inv1;
        sE[(c + 1) * 132 + mloc + 8] = eacc[j][3] * inv1;
    }
    __syncthreads();
    for (int u = tid; u < 2048; u += 256) {
        int c = u >> 5, q = u & 31;
        float4 v = *(float4*)&sE[c * 132 + q * 4];
        *(float4*)&g_E[(((b << 6) + c) << 12) + m0 + q * 4] = v;
    }
}

// ================= Kernel 3: conv3x3 + BN + ReLU + residual =================
__global__ void __launch_bounds__(128, 1) conv_kernel(
    const float* __restrict__ Hp,
    const float* __restrict__ cw, const float* __restrict__ cb,
    const float* __restrict__ gamma, const float* __restrict__ beta,
    const float* __restrict__ mean, const float* __restrict__ var,
    float* __restrict__ out)
{
    extern __shared__ float sW[];  // [ic*9+kk][oc]
    const int tid = threadIdx.x, b = blockIdx.y, y0 = blockIdx.x << 1;
    for (int i = tid; i < 64 * 64 * 9; i += 128) {
        int oc = i / 576, rem = i - oc * 576, ic = rem / 9, kk = rem - ic * 9;
        sW[(ic * 9 + kk) * 64 + oc] = cw[i];
    }
    __syncthreads();
    const int y = y0 + (tid >> 6), x = tid & 63;
    float2 acc[32];
    #pragma unroll
    for (int i = 0; i < 32; i++) acc[i] = make_float2(0.f, 0.f);
    for (int ic = 0; ic < 64; ic++) {
        const float* src = &g_E[(((b << 6) + ic) << 12)];
        float in9[9];
        #pragma unroll
        for (int dy = 0; dy < 3; dy++) {
            int yy = y + dy - 1; bool yok = (yy >= 0) && (yy < 64);
            #pragma unroll
            for (int dx = 0; dx < 3; dx++) {
                int xx = x + dx - 1;
                in9[dy * 3 + dx] = (yok && xx >= 0 && xx < 64) ? src[(yy << 6) + xx] : 0.f;
            }
        }
        #pragma unroll
        for (int kk = 0; kk < 9; kk++) {
            float iv = in9[kk];
            const float* wr = &sW[(ic * 9 + kk) << 6];
            #pragma unroll
            for (int q = 0; q < 32; q++) {
                float2 w = *(const float2*)&wr[q << 1];
                acc[q].x = fmaf(iv, w.x, acc[q].x);
                acc[q].y = fmaf(iv, w.y, acc[q].y);
            }
        }
    }
    const int pix = (y << 6) + x;
    #pragma unroll
    for (int q = 0; q < 32; q++) {
        #pragma unroll
        for (int h = 0; h < 2; h++) {
            int oc = 2 * q + h;
            float v = (h ? acc[q].y : acc[q].x) + cb[oc];
            v = (v - mean[oc]) * (gamma[oc] * rsqrtf(var[oc] + 1e-5f)) + beta[oc];
            v = fmaxf(v, 0.f);
            int idx = (((b << 6) + oc) << 12) + pix;
            out[idx] = Hp[idx] + v;
        }
    }
}

extern "C" void kernel_launch(void* const* d_in, const int* in_sizes, int n_in,
                              void* d_out, int out_size)
{
    const float* Hp = (const float*)d_in[0];
    const float* Lp = (const float*)d_in[1];
    const float* tw = (const float*)d_in[2];  const float* tb = (const float*)d_in[3];
    const float* pw = (const float*)d_in[4];  const float* pb = (const float*)d_in[5];
    const float* gw = (const float*)d_in[6];  const float* gb = (const float*)d_in[7];
    const float* cw = (const float*)d_in[8];  const float* cb = (const float*)d_in[9];
    const float* gamma = (const float*)d_in[10]; const float* beta = (const float*)d_in[11];
    const float* mean = (const float*)d_in[12];  const float* var = (const float*)d_in[13];
    float* out = (float*)d_out;

    const int smem_proj = (128 * 128 + 64 * 128) * 4;
    const int smem_conv = 64 * 64 * 9 * 4;
    cudaFuncSetAttribute(proj_kernel, cudaFuncAttributeMaxDynamicSharedMemorySize, smem_proj);
    cudaFuncSetAttribute(attn_kernel, cudaFuncAttributeMaxDynamicSharedMemorySize, ATTN_SMEM);
    cudaFuncSetAttribute(conv_kernel, cudaFuncAttributeMaxDynamicSharedMemorySize, smem_conv);

    proj_kernel<<<dim3(32, 3, 4), 256, smem_proj>>>(Hp, Lp, tw, tb, pw, pb, gw, gb);
    attn_kernel<<<dim3(32, 4), 256, ATTN_SMEM>>>();
    conv_kernel<<<dim3(32, 4), 128, smem_conv>>>(Hp, cw, cb, gamma, beta, mean, var, out);
}